// round 1
// baseline (speedup 1.0000x reference)
#include <cuda_runtime.h>
#include <mma.h>

using namespace nvcuda;

#define DIMX   256
#define HEADS  8
#define BATCH  256
#define NQ     256
#define NK     576
#define DH     32
#define SCALE  0.17677669529663687f

// ---------------- scratch (device globals: no allocations allowed) ----------
__device__ __align__(16) float g_qp[(size_t)BATCH * NQ * DIMX];        // 67 MB  [B,Nq,H*Dh]
__device__ __align__(16) float g_kvp[(size_t)BATCH * NK * 2 * DIMX];   // 302 MB [B,Nk,2*H*Dh]
__device__ __align__(16) float g_bias[(size_t)HEADS * NQ * NK];        // 4.7 MB [H,Nq,Nk]
__device__ __align__(16) float g_ao[(size_t)BATCH * NQ * DIMX];        // 67 MB  [B,Nq,H*Dh]

typedef wmma::fragment<wmma::matrix_a, 16, 16, 8, wmma::precision::tf32, wmma::row_major> FragA;
typedef wmma::fragment<wmma::matrix_b, 16, 16, 8, wmma::precision::tf32, wmma::row_major> FragBR;
typedef wmma::fragment<wmma::matrix_b, 16, 16, 8, wmma::precision::tf32, wmma::col_major> FragBC;
typedef wmma::fragment<wmma::accumulator, 16, 16, 8, float> FragC;

template <class F>
__device__ __forceinline__ void cvt_tf32(F& f) {
#pragma unroll
    for (int i = 0; i < f.num_elements; i++) f.x[i] = wmma::__float_to_tf32(f.x[i]);
}

// ---------------- kernel 0: gather relative-position bias -> [H,Nq,Nk] ------
__global__ void bias_gather(const float* __restrict__ table,
                            const int* __restrict__ rel,
                            float* __restrict__ bias_mat) {
    int p = blockIdx.x * 256 + threadIdx.x;
    if (p >= NQ * NK) return;
    int idx = rel[p];
    const float4* t4 = reinterpret_cast<const float4*>(table + (size_t)idx * 8);
    float4 a = t4[0];
    float4 b = t4[1];
    const int PL = NQ * NK;
    bias_mat[0 * PL + p] = a.x;
    bias_mat[1 * PL + p] = a.y;
    bias_mat[2 * PL + p] = a.z;
    bias_mat[3 * PL + p] = a.w;
    bias_mat[4 * PL + p] = b.x;
    bias_mat[5 * PL + p] = b.y;
    bias_mat[6 * PL + p] = b.z;
    bias_mat[7 * PL + p] = b.w;
}

// ---------------- generic tf32 GEMM: C[M,N] = A[M,256] @ W[256,N] + bias ----
// block tile 128x64, BK=32, 8 warps (4x2), warp tile 32x32 (2x2 wmma frags)
__global__ void gemm_tf32(const float* __restrict__ A,
                          const float* __restrict__ W,
                          const float* __restrict__ bias,
                          float* __restrict__ C, int N) {
    extern __shared__ float sm[];
    float* As = sm;                 // 128 x 36
    float* Bs = sm + 128 * 36;      // 32 x 68
    float* Cs = sm;                 // 128 x 72 (reuse after mainloop)

    const int tid = threadIdx.x;
    const int w = tid >> 5;
    const int wm = w >> 1;          // 0..3
    const int wn = w & 1;           // 0..1
    const int bm = blockIdx.y, bn = blockIdx.x;

    const float* Ab = A + (size_t)bm * 128 * 256;
    const float* Wb = W + bn * 64;

    FragC acc[2][2];
#pragma unroll
    for (int mt = 0; mt < 2; mt++)
#pragma unroll
        for (int nt = 0; nt < 2; nt++) wmma::fill_fragment(acc[mt][nt], 0.f);

    for (int kt = 0; kt < 8; kt++) {
        // load A tile 128x32 (float4)
#pragma unroll
        for (int it = 0; it < 4; it++) {
            int i = it * 256 + tid;          // 0..1023 (float4 index)
            int r = i >> 3, c4 = i & 7;
            float4 v = *(const float4*)(Ab + (size_t)r * 256 + kt * 32 + c4 * 4);
            *(float4*)(As + r * 36 + c4 * 4) = v;
        }
        // load W tile 32x64 (float4)
#pragma unroll
        for (int it = 0; it < 2; it++) {
            int i = it * 256 + tid;          // 0..511
            int r = i >> 4, c4 = i & 15;
            float4 v = *(const float4*)(Wb + (size_t)(kt * 32 + r) * N + c4 * 4);
            *(float4*)(Bs + r * 68 + c4 * 4) = v;
        }
        __syncthreads();
#pragma unroll
        for (int kk = 0; kk < 4; kk++) {
            FragA af[2];
            FragBR bf[2];
#pragma unroll
            for (int mt = 0; mt < 2; mt++) {
                wmma::load_matrix_sync(af[mt], As + (wm * 32 + mt * 16) * 36 + kk * 8, 36);
                cvt_tf32(af[mt]);
            }
#pragma unroll
            for (int nt = 0; nt < 2; nt++) {
                wmma::load_matrix_sync(bf[nt], Bs + (kk * 8) * 68 + wn * 32 + nt * 16, 68);
                cvt_tf32(bf[nt]);
            }
#pragma unroll
            for (int mt = 0; mt < 2; mt++)
#pragma unroll
                for (int nt = 0; nt < 2; nt++)
                    wmma::mma_sync(acc[mt][nt], af[mt], bf[nt], acc[mt][nt]);
        }
        __syncthreads();
    }

    // epilogue: stage to smem, add bias, write coalesced
#pragma unroll
    for (int mt = 0; mt < 2; mt++)
#pragma unroll
        for (int nt = 0; nt < 2; nt++)
            wmma::store_matrix_sync(Cs + (wm * 32 + mt * 16) * 72 + wn * 32 + nt * 16,
                                    acc[mt][nt], 72, wmma::mem_row_major);
    __syncthreads();
#pragma unroll
    for (int it = 0; it < 32; it++) {
        int e = it * 256 + tid;
        int r = e >> 6, c = e & 63;
        C[((size_t)bm * 128 + r) * N + bn * 64 + c] = Cs[r * 72 + c] + bias[bn * 64 + c];
    }
}

// ---------------- fused attention per (b, h, 32-row q-tile) ------------------
// smem: S 32x584 scores | Qs 32x36 | Op 8x1024 partials  = 112128 B
__global__ void attn_kernel(const float* __restrict__ qp,
                            const float* __restrict__ kvp,
                            const float* __restrict__ bias_mat,
                            float* __restrict__ ao) {
    extern __shared__ float sm[];
    float* S = sm;                   // 32 x 584
    float* Qs = sm + 32 * 584;       // 32 x 36
    float* Op = Qs + 32 * 36;        // 8 x (32*32)

    const int bx = blockIdx.x;
    const int qt = bx & 7, h = (bx >> 3) & 7, b = bx >> 6;
    const int q0 = qt * 32;
    const int tid = threadIdx.x, w = tid >> 5, lane = tid & 31;
    const int LDKV = 2 * DIMX;

    // load Q tile 32x32
    for (int i = tid; i < 32 * 32; i += 256) {
        int r = i >> 5, c = i & 31;
        Qs[r * 36 + c] = qp[((size_t)(b * NQ + q0 + r)) * DIMX + h * DH + c];
    }
    __syncthreads();

    FragA qf[2][4];
#pragma unroll
    for (int mt = 0; mt < 2; mt++)
#pragma unroll
        for (int kk = 0; kk < 4; kk++) {
            wmma::load_matrix_sync(qf[mt][kk], Qs + (mt * 16) * 36 + kk * 8, 36);
            cvt_tf32(qf[mt][kk]);
        }

    // phase 1: S = Q @ K^T (warp-cyclic over 36 n-tiles)
    const float* Kb = kvp + ((size_t)b * NK) * LDKV + h * DH;
    for (int t = w; t < 36; t += 8) {
        FragC acc[2];
        wmma::fill_fragment(acc[0], 0.f);
        wmma::fill_fragment(acc[1], 0.f);
#pragma unroll
        for (int kk = 0; kk < 4; kk++) {
            FragBC bf;
            wmma::load_matrix_sync(bf, Kb + (size_t)(t * 16) * LDKV + kk * 8, LDKV);
            cvt_tf32(bf);
            wmma::mma_sync(acc[0], qf[0][kk], bf, acc[0]);
            wmma::mma_sync(acc[1], qf[1][kk], bf, acc[1]);
        }
        wmma::store_matrix_sync(S + t * 16, acc[0], 584, wmma::mem_row_major);
        wmma::store_matrix_sync(S + 16 * 584 + t * 16, acc[1], 584, wmma::mem_row_major);
    }
    __syncthreads();

    // scale + relative-position bias
    {
        const float* bm = bias_mat + (size_t)h * NQ * NK + (size_t)q0 * NK;
        for (int i = tid; i < 32 * NK; i += 256) {
            int r = i / NK, c = i - r * NK;
            S[r * 584 + c] = S[r * 584 + c] * SCALE + bm[r * NK + c];
        }
    }
    __syncthreads();

    // softmax: warp w owns rows w*4 .. w*4+3 (full-warp reductions)
#pragma unroll
    for (int rr = 0; rr < 4; rr++) {
        float* row = S + (w * 4 + rr) * 584;
        float mx = -1e30f;
        for (int c = lane; c < NK; c += 32) mx = fmaxf(mx, row[c]);
#pragma unroll
        for (int o = 16; o; o >>= 1) mx = fmaxf(mx, __shfl_xor_sync(0xffffffffu, mx, o));
        float s = 0.f;
        for (int c = lane; c < NK; c += 32) {
            float e = __expf(row[c] - mx);
            row[c] = e;
            s += e;
        }
#pragma unroll
        for (int o = 16; o; o >>= 1) s += __shfl_xor_sync(0xffffffffu, s, o);
        float inv = 1.f / s;
        for (int c = lane; c < NK; c += 32) row[c] *= inv;
    }
    __syncthreads();

    // phase 3: O = P @ V, k-split across 8 warps (9 k-steps each)
    FragC oacc[2][2];
#pragma unroll
    for (int mt = 0; mt < 2; mt++)
#pragma unroll
        for (int nt = 0; nt < 2; nt++) wmma::fill_fragment(oacc[mt][nt], 0.f);

    const float* Vb = kvp + ((size_t)b * NK) * LDKV + DIMX + h * DH;
    for (int ks = w * 9; ks < (w + 1) * 9; ks++) {
        FragA pf[2];
        FragBR vf[2];
#pragma unroll
        for (int mt = 0; mt < 2; mt++) {
            wmma::load_matrix_sync(pf[mt], S + (mt * 16) * 584 + ks * 8, 584);
            cvt_tf32(pf[mt]);
        }
#pragma unroll
        for (int nt = 0; nt < 2; nt++) {
            wmma::load_matrix_sync(vf[nt], Vb + (size_t)(ks * 8) * LDKV + nt * 16, LDKV);
            cvt_tf32(vf[nt]);
        }
#pragma unroll
        for (int mt = 0; mt < 2; mt++)
#pragma unroll
            for (int nt = 0; nt < 2; nt++)
                wmma::mma_sync(oacc[mt][nt], pf[mt], vf[nt], oacc[mt][nt]);
    }
#pragma unroll
    for (int mt = 0; mt < 2; mt++)
#pragma unroll
        for (int nt = 0; nt < 2; nt++)
            wmma::store_matrix_sync(Op + w * 1024 + (mt * 16) * 32 + nt * 16,
                                    oacc[mt][nt], 32, wmma::mem_row_major);
    __syncthreads();

    // cross-warp reduction + write [B, Nq, H*Dh]
    for (int i = tid; i < 1024; i += 256) {
        float s = 0.f;
#pragma unroll
        for (int ww = 0; ww < 8; ww++) s += Op[ww * 1024 + i];
        int r = i >> 5, c = i & 31;
        ao[((size_t)(b * NQ + q0 + r)) * DIMX + h * DH + c] = s;
    }
}

// ---------------- launch ----------------------------------------------------
extern "C" void kernel_launch(void* const* d_in, const int* in_sizes, int n_in,
                              void* d_out, int out_size) {
    const float* q_w = (const float*)d_in[0];
    const float* kv_w = (const float*)d_in[1];
    const float* q_W = (const float*)d_in[2];
    const float* q_b = (const float*)d_in[3];
    const float* kv_W = (const float*)d_in[4];
    const float* kv_b = (const float*)d_in[5];
    const float* proj_W = (const float*)d_in[6];
    const float* proj_b = (const float*)d_in[7];
    const float* bias_table = (const float*)d_in[8];
    const int* rel_index = (const int*)d_in[9];
    float* out = (float*)d_out;

    float *qp, *kvp, *bias, *ao;
    cudaGetSymbolAddress((void**)&qp, g_qp);
    cudaGetSymbolAddress((void**)&kvp, g_kvp);
    cudaGetSymbolAddress((void**)&bias, g_bias);
    cudaGetSymbolAddress((void**)&ao, g_ao);

    cudaFuncSetAttribute(attn_kernel, cudaFuncAttributeMaxDynamicSharedMemorySize, 112128);

    const int GEMM_SMEM = 128 * 72 * 4;  // 36864 B (covers As+Bs overlay too)

    bias_gather<<<(NQ * NK + 255) / 256, 256>>>(bias_table, rel_index, bias);
    gemm_tf32<<<dim3(4, 512), 256, GEMM_SMEM>>>(q_w, q_W, q_b, qp, 256);
    gemm_tf32<<<dim3(8, 1152), 256, GEMM_SMEM>>>(kv_w, kv_W, kv_b, kvp, 512);
    attn_kernel<<<BATCH * HEADS * 8, 256, 112128>>>(qp, kvp, bias, ao);
    gemm_tf32<<<dim3(4, 512), 256, GEMM_SMEM>>>(ao, proj_W, proj_b, out, 256);
}

// round 4
// speedup vs baseline: 1.1832x; 1.1832x over previous
#include <cuda_runtime.h>
#include <cstdint>
#include <mma.h>

using namespace nvcuda;

#define DIMX   256
#define HEADS  8
#define BATCH  256
#define NQ     256
#define NK     576
#define DH     32
#define SCALE  0.17677669529663687f

// ---------------- scratch (device globals: no allocations allowed) ----------
__device__ __align__(16) float g_qp[(size_t)BATCH * NQ * DIMX];        // 67 MB  [B,Nq,H*Dh]
__device__ __align__(16) float g_kvp[(size_t)BATCH * NK * 2 * DIMX];   // 302 MB [B,Nk,2*H*Dh]
__device__ __align__(16) float g_bias[(size_t)HEADS * NQ * NK];        // 4.7 MB [H,Nq,Nk]
__device__ __align__(16) float g_ao[(size_t)BATCH * NQ * DIMX];        // 67 MB  [B,Nq,H*Dh]

typedef wmma::fragment<wmma::matrix_a, 16, 16, 8, wmma::precision::tf32, wmma::row_major> FragA;
typedef wmma::fragment<wmma::matrix_b, 16, 16, 8, wmma::precision::tf32, wmma::row_major> FragBR;
typedef wmma::fragment<wmma::matrix_b, 16, 16, 8, wmma::precision::tf32, wmma::col_major> FragBC;
typedef wmma::fragment<wmma::accumulator, 16, 16, 8, float> FragC;

template <class F>
__device__ __forceinline__ void cvt_tf32(F& f) {
#pragma unroll
    for (int i = 0; i < f.num_elements; i++) f.x[i] = wmma::__float_to_tf32(f.x[i]);
}

__device__ __forceinline__ void cp16(uint32_t dst, const void* src) {
    asm volatile("cp.async.cg.shared.global [%0], [%1], 16;\n" :: "r"(dst), "l"(src));
}
__device__ __forceinline__ void cp_commit() {
    asm volatile("cp.async.commit_group;\n");
}
template <int N>
__device__ __forceinline__ void cp_wait() {
    asm volatile("cp.async.wait_group %0;\n" :: "n"(N));
}

// ---------------- kernel 0: gather relative-position bias -> [H,Nq,Nk] ------
__global__ void bias_gather(const float* __restrict__ table,
                            const int* __restrict__ rel,
                            float* __restrict__ bias_mat) {
    int p = blockIdx.x * 256 + threadIdx.x;
    if (p >= NQ * NK) return;
    int idx = rel[p];
    const float4* t4 = reinterpret_cast<const float4*>(table + (size_t)idx * 8);
    float4 a = t4[0];
    float4 b = t4[1];
    const int PL = NQ * NK;
    bias_mat[0 * PL + p] = a.x;
    bias_mat[1 * PL + p] = a.y;
    bias_mat[2 * PL + p] = a.z;
    bias_mat[3 * PL + p] = a.w;
    bias_mat[4 * PL + p] = b.x;
    bias_mat[5 * PL + p] = b.y;
    bias_mat[6 * PL + p] = b.z;
    bias_mat[7 * PL + p] = b.w;
}

// ---------------- tf32 GEMM: C[M,N] = A[M,256] @ W[256,N] + bias ------------
// block tile 128x128, BK=32, 8 warps (4x2), warp tile 32x64 (2x4 frags)
// double-buffered cp.async smem pipeline
__global__ void __launch_bounds__(256, 2) gemm_tf32(const float* __restrict__ A,
                                                    const float* __restrict__ W,
                                                    const float* __restrict__ bias,
                                                    float* __restrict__ C, int N) {
    extern __shared__ float sm[];
    float* As = sm;                    // 2 x 128 x 36 = 9216 floats
    float* Bs = sm + 2 * 128 * 36;     // 2 x 32 x 132 = 8448 floats
    float* Cs = sm;                    // reuse: 128 x 132 = 16896 floats

    const int tid = threadIdx.x;
    const int w = tid >> 5;
    const int wm = w >> 1;             // 0..3
    const int wn = w & 1;              // 0..1
    const int bm = blockIdx.y, bn = blockIdx.x;

    const float* Ab = A + (size_t)bm * 128 * 256;
    const float* Wb = W + bn * 128;

    uint32_t sA = (uint32_t)__cvta_generic_to_shared(As);
    uint32_t sB = (uint32_t)__cvta_generic_to_shared(Bs);

    FragC acc[2][4];
#pragma unroll
    for (int mt = 0; mt < 2; mt++)
#pragma unroll
        for (int nt = 0; nt < 4; nt++) wmma::fill_fragment(acc[mt][nt], 0.f);

    auto prefA = [&](int kt, int buf) {
#pragma unroll
        for (int it = 0; it < 4; it++) {
            int i = it * 256 + tid;        // 1024 float4
            int r = i >> 3, c4 = i & 7;
            cp16(sA + (buf * 4608 + r * 36 + c4 * 4) * 4,
                 Ab + (size_t)r * 256 + kt * 32 + c4 * 4);
        }
    };
    auto prefB = [&](int kt, int buf) {
#pragma unroll
        for (int it = 0; it < 4; it++) {
            int i = it * 256 + tid;        // 1024 float4
            int r = i >> 5, c4 = i & 31;
            cp16(sB + (buf * 4224 + r * 132 + c4 * 4) * 4,
                 Wb + (size_t)(kt * 32 + r) * N + c4 * 4);
        }
    };

    prefA(0, 0); prefB(0, 0); cp_commit();

    for (int kt = 0; kt < 8; kt++) {
        if (kt < 7) { prefA(kt + 1, (kt + 1) & 1); prefB(kt + 1, (kt + 1) & 1); cp_commit(); }
        if (kt < 7) cp_wait<1>(); else cp_wait<0>();
        __syncthreads();
        const float* Asb = As + (kt & 1) * 4608;
        const float* Bsb = Bs + (kt & 1) * 4224;
#pragma unroll
        for (int kk = 0; kk < 4; kk++) {
            FragA af[2];
            FragBR bf[4];
#pragma unroll
            for (int mt = 0; mt < 2; mt++) {
                wmma::load_matrix_sync(af[mt], Asb + (wm * 32 + mt * 16) * 36 + kk * 8, 36);
                cvt_tf32(af[mt]);
            }
#pragma unroll
            for (int nt = 0; nt < 4; nt++) {
                wmma::load_matrix_sync(bf[nt], Bsb + (kk * 8) * 132 + wn * 64 + nt * 16, 132);
                cvt_tf32(bf[nt]);
            }
#pragma unroll
            for (int mt = 0; mt < 2; mt++)
#pragma unroll
                for (int nt = 0; nt < 4; nt++)
                    wmma::mma_sync(acc[mt][nt], af[mt], bf[nt], acc[mt][nt]);
        }
        __syncthreads();
    }

    // epilogue: stage to smem, add bias, write coalesced
#pragma unroll
    for (int mt = 0; mt < 2; mt++)
#pragma unroll
        for (int nt = 0; nt < 4; nt++)
            wmma::store_matrix_sync(Cs + (wm * 32 + mt * 16) * 132 + wn * 64 + nt * 16,
                                    acc[mt][nt], 132, wmma::mem_row_major);
    __syncthreads();
#pragma unroll
    for (int it = 0; it < 64; it++) {
        int e = it * 256 + tid;
        int r = e >> 7, c = e & 127;
        C[((size_t)bm * 128 + r) * N + bn * 128 + c] = Cs[r * 132 + c] + bias[bn * 128 + c];
    }
}

// ---------------- fused attention per (b, h, 64-row q-tile) ------------------
// smem: S 64x588 | Qs/Os 64x36 | KV double-buffer 2x64x36 | inv 64
__global__ void __launch_bounds__(256) attn_kernel(const float* __restrict__ qp,
                                                   const float* __restrict__ kvp,
                                                   const float* __restrict__ bias_mat,
                                                   float* __restrict__ ao) {
    extern __shared__ float sm[];
    float* S  = sm;                        // 64 x 588
    float* Qs = sm + 64 * 588;             // 64 x 36 (reused as O staging)
    float* KV = Qs + 64 * 36;              // 2 x 64 x 36
    float* inv = KV + 2 * 64 * 36;         // 64

    const int bx = blockIdx.x;
    const int qt = bx & 3, h = (bx >> 2) & 7, b = bx >> 5;
    const int q0 = qt * 64;
    const int tid = threadIdx.x, w = tid >> 5, lane = tid & 31;
    const int LDKV = 2 * DIMX;

    const float* Kb = kvp + ((size_t)b * NK) * LDKV + h * DH;
    const float* Vb = Kb + DIMX;
    uint32_t sKV = (uint32_t)__cvta_generic_to_shared(KV);

    auto prefKV = [&](const float* base, int chunk, int buf) {
#pragma unroll
        for (int it = 0; it < 2; it++) {
            int i = it * 256 + tid;        // 512 float4 (64 rows x 8)
            int r = i >> 3, c4 = i & 7;
            cp16(sKV + (buf * 2304 + r * 36 + c4 * 4) * 4,
                 base + (size_t)(chunk * 64 + r) * LDKV + c4 * 4);
        }
    };

    prefKV(Kb, 0, 0); cp_commit();

    // load Q tile 64x32 (float4)
#pragma unroll
    for (int it = 0; it < 2; it++) {
        int i = it * 256 + tid;
        int r = i >> 3, c4 = i & 7;
        float4 v = *(const float4*)(qp + ((size_t)(b * NQ + q0 + r)) * DIMX + h * DH + c4 * 4);
        *(float4*)(Qs + r * 36 + c4 * 4) = v;
    }
    __syncthreads();

    const int wm = w >> 1, wn = w & 1;     // phase-1 layout 4m x 2n
    FragA qf[4];
#pragma unroll
    for (int kk = 0; kk < 4; kk++) {
        wmma::load_matrix_sync(qf[kk], Qs + (wm * 16) * 36 + kk * 8, 36);
        cvt_tf32(qf[kk]);
    }

    // phase 1: S = Q @ K^T over 9 chunks of 64 keys
    for (int c = 0; c < 9; c++) {
        if (c < 8) { prefKV(Kb, c + 1, (c + 1) & 1); cp_commit(); }
        if (c < 8) cp_wait<1>(); else cp_wait<0>();
        __syncthreads();
        const float* Ks = KV + (c & 1) * 2304;
        FragC acc[2];
        wmma::fill_fragment(acc[0], 0.f);
        wmma::fill_fragment(acc[1], 0.f);
#pragma unroll
        for (int kk = 0; kk < 4; kk++) {
            FragBC bf[2];
#pragma unroll
            for (int nt = 0; nt < 2; nt++) {
                wmma::load_matrix_sync(bf[nt], Ks + (wn * 32 + nt * 16) * 36 + kk * 8, 36);
                cvt_tf32(bf[nt]);
            }
            wmma::mma_sync(acc[0], qf[kk], bf[0], acc[0]);
            wmma::mma_sync(acc[1], qf[kk], bf[1], acc[1]);
        }
#pragma unroll
        for (int nt = 0; nt < 2; nt++)
            wmma::store_matrix_sync(S + (wm * 16) * 588 + c * 64 + wn * 32 + nt * 16,
                                    acc[nt], 588, wmma::mem_row_major);
        __syncthreads();
    }

    // prefetch V chunk 0 so it overlaps the softmax
    prefKV(Vb, 0, 0); cp_commit();

    // softmax (scale + bias fused; normalization deferred via inv[])
    {
        const float* bm = bias_mat + (size_t)h * NQ * NK + (size_t)(q0) * NK;
#pragma unroll
        for (int rr = 0; rr < 8; rr++) {
            int r = w * 8 + rr;
            float* row = S + r * 588;
            const float* br = bm + (size_t)r * NK;
            float mx = -1e30f;
            for (int c = lane; c < NK; c += 32) {
                float v = row[c] * SCALE + br[c];
                row[c] = v;
                mx = fmaxf(mx, v);
            }
#pragma unroll
            for (int o = 16; o; o >>= 1) mx = fmaxf(mx, __shfl_xor_sync(0xffffffffu, mx, o));
            float s = 0.f;
            for (int c = lane; c < NK; c += 32) {
                float e = __expf(row[c] - mx);
                row[c] = e;
                s += e;
            }
#pragma unroll
            for (int o = 16; o; o >>= 1) s += __shfl_xor_sync(0xffffffffu, s, o);
            if (lane == 0) inv[r] = 1.f / s;
        }
    }
    __syncthreads();

    // phase 3: O = P @ V (warp layout 4m x 2n, 16x16 output per warp)
    FragC oa, ob;
    wmma::fill_fragment(oa, 0.f);
    wmma::fill_fragment(ob, 0.f);
    for (int c = 0; c < 9; c++) {
        if (c < 8) { prefKV(Vb, c + 1, (c + 1) & 1); cp_commit(); }
        if (c < 8) cp_wait<1>(); else cp_wait<0>();
        __syncthreads();
        const float* Vs = KV + (c & 1) * 2304;
#pragma unroll
        for (int kk = 0; kk < 8; kk++) {
            FragA pf;
            FragBR vf;
            wmma::load_matrix_sync(pf, S + (wm * 16) * 588 + c * 64 + kk * 8, 588);
            cvt_tf32(pf);
            wmma::load_matrix_sync(vf, Vs + (kk * 8) * 36 + wn * 16, 36);
            cvt_tf32(vf);
            if (kk & 1) wmma::mma_sync(ob, pf, vf, ob);
            else        wmma::mma_sync(oa, pf, vf, oa);
        }
        __syncthreads();
    }
#pragma unroll
    for (int i = 0; i < oa.num_elements; i++) oa.x[i] += ob.x[i];

    // stage O (reuse Qs), apply deferred softmax normalization, write out
    wmma::store_matrix_sync(Qs + (wm * 16) * 36 + wn * 16, oa, 36, wmma::mem_row_major);
    __syncthreads();
#pragma unroll
    for (int it = 0; it < 8; it++) {
        int i = it * 256 + tid;
        int r = i >> 5, c = i & 31;
        ao[((size_t)(b * NQ + q0 + r)) * DIMX + h * DH + c] = Qs[r * 36 + c] * inv[r];
    }
}

// ---------------- launch ----------------------------------------------------
extern "C" void kernel_launch(void* const* d_in, const int* in_sizes, int n_in,
                              void* d_out, int out_size) {
    const float* q_w = (const float*)d_in[0];
    const float* kv_w = (const float*)d_in[1];
    const float* q_W = (const float*)d_in[2];
    const float* q_b = (const float*)d_in[3];
    const float* kv_W = (const float*)d_in[4];
    const float* kv_b = (const float*)d_in[5];
    const float* proj_W = (const float*)d_in[6];
    const float* proj_b = (const float*)d_in[7];
    const float* bias_table = (const float*)d_in[8];
    const int* rel_index = (const int*)d_in[9];
    float* out = (float*)d_out;

    float *qp, *kvp, *bias, *ao;
    cudaGetSymbolAddress((void**)&qp, g_qp);
    cudaGetSymbolAddress((void**)&kvp, g_kvp);
    cudaGetSymbolAddress((void**)&bias, g_bias);
    cudaGetSymbolAddress((void**)&ao, g_ao);

    const int GEMM_SMEM = (2 * 128 * 36 + 2 * 32 * 132) * 4;   // 70656 B
    const int ATTN_SMEM = (64 * 588 + 64 * 36 + 2 * 64 * 36 + 64) * 4;  // 178432 B

    cudaFuncSetAttribute(gemm_tf32, cudaFuncAttributeMaxDynamicSharedMemorySize, GEMM_SMEM);
    cudaFuncSetAttribute(attn_kernel, cudaFuncAttributeMaxDynamicSharedMemorySize, ATTN_SMEM);

    bias_gather<<<(NQ * NK + 255) / 256, 256>>>(bias_table, rel_index, bias);
    gemm_tf32<<<dim3(2, 512), 256, GEMM_SMEM>>>(q_w, q_W, q_b, qp, 256);
    gemm_tf32<<<dim3(4, 1152), 256, GEMM_SMEM>>>(kv_w, kv_W, kv_b, kvp, 512);
    attn_kernel<<<BATCH * HEADS * 4, 256, ATTN_SMEM>>>(qp, kvp, bias, ao);
    gemm_tf32<<<dim3(2, 512), 256, GEMM_SMEM>>>(ao, proj_W, proj_b, out, 256);
}

// round 5
// speedup vs baseline: 1.3655x; 1.1541x over previous
#include <cuda_runtime.h>
#include <cstdint>
#include <mma.h>

using namespace nvcuda;

#define DIMX   256
#define HEADS  8
#define BATCH  256
#define NQ     256
#define NK     576
#define DH     32
#define SCALE  0.17677669529663687f

// ---------------- scratch (device globals: no allocations allowed) ----------
__device__ __align__(16) float g_qp[(size_t)BATCH * NQ * DIMX];        // 67 MB  [B,Nq,H*Dh]
__device__ __align__(16) float g_kvp[(size_t)BATCH * NK * 2 * DIMX];   // 302 MB [B,Nk,2*H*Dh]
__device__ __align__(16) float g_bias[(size_t)HEADS * NQ * NK];        // 4.7 MB [H,Nq,Nk]
__device__ __align__(16) float g_ao[(size_t)BATCH * NQ * DIMX];        // 67 MB  [B,Nq,H*Dh]

typedef wmma::fragment<wmma::matrix_a, 16, 16, 8, wmma::precision::tf32, wmma::row_major> FragA;
typedef wmma::fragment<wmma::matrix_b, 16, 16, 8, wmma::precision::tf32, wmma::row_major> FragBR;
typedef wmma::fragment<wmma::matrix_b, 16, 16, 8, wmma::precision::tf32, wmma::col_major> FragBC;
typedef wmma::fragment<wmma::accumulator, 16, 16, 8, float> FragC;

template <class F>
__device__ __forceinline__ void cvt_tf32(F& f) {
#pragma unroll
    for (int i = 0; i < f.num_elements; i++) f.x[i] = wmma::__float_to_tf32(f.x[i]);
}

__device__ __forceinline__ void cp16(uint32_t dst, const void* src) {
    asm volatile("cp.async.cg.shared.global [%0], [%1], 16;\n" :: "r"(dst), "l"(src));
}
__device__ __forceinline__ void cp_commit() {
    asm volatile("cp.async.commit_group;\n");
}
template <int N>
__device__ __forceinline__ void cp_wait() {
    asm volatile("cp.async.wait_group %0;\n" :: "n"(N));
}

// ---------------- kernel 0: gather relative-position bias -> [H,Nq,Nk] ------
__global__ void bias_gather(const float* __restrict__ table,
                            const int* __restrict__ rel,
                            float* __restrict__ bias_mat) {
    int p = blockIdx.x * 256 + threadIdx.x;
    if (p >= NQ * NK) return;
    int idx = rel[p];
    const float4* t4 = reinterpret_cast<const float4*>(table + (size_t)idx * 8);
    float4 a = t4[0];
    float4 b = t4[1];
    const int PL = NQ * NK;
    bias_mat[0 * PL + p] = a.x;
    bias_mat[1 * PL + p] = a.y;
    bias_mat[2 * PL + p] = a.z;
    bias_mat[3 * PL + p] = a.w;
    bias_mat[4 * PL + p] = b.x;
    bias_mat[5 * PL + p] = b.y;
    bias_mat[6 * PL + p] = b.z;
    bias_mat[7 * PL + p] = b.w;
}

// ---------------- tf32 GEMM: C[M,N] = A[M,256] @ W[256,N] + bias ------------
__global__ void __launch_bounds__(256, 2) gemm_tf32(const float* __restrict__ A,
                                                    const float* __restrict__ W,
                                                    const float* __restrict__ bias,
                                                    float* __restrict__ C, int N) {
    extern __shared__ float sm[];
    float* As = sm;                    // 2 x 128 x 36
    float* Bs = sm + 2 * 128 * 36;     // 2 x 32 x 132
    float* Cs = sm;                    // reuse: 128 x 132

    const int tid = threadIdx.x;
    const int w = tid >> 5;
    const int wm = w >> 1;
    const int wn = w & 1;
    const int bm = blockIdx.y, bn = blockIdx.x;

    const float* Ab = A + (size_t)bm * 128 * 256;
    const float* Wb = W + bn * 128;

    uint32_t sA = (uint32_t)__cvta_generic_to_shared(As);
    uint32_t sB = (uint32_t)__cvta_generic_to_shared(Bs);

    FragC acc[2][4];
#pragma unroll
    for (int mt = 0; mt < 2; mt++)
#pragma unroll
        for (int nt = 0; nt < 4; nt++) wmma::fill_fragment(acc[mt][nt], 0.f);

    auto prefA = [&](int kt, int buf) {
#pragma unroll
        for (int it = 0; it < 4; it++) {
            int i = it * 256 + tid;
            int r = i >> 3, c4 = i & 7;
            cp16(sA + (buf * 4608 + r * 36 + c4 * 4) * 4,
                 Ab + (size_t)r * 256 + kt * 32 + c4 * 4);
        }
    };
    auto prefB = [&](int kt, int buf) {
#pragma unroll
        for (int it = 0; it < 4; it++) {
            int i = it * 256 + tid;
            int r = i >> 5, c4 = i & 31;
            cp16(sB + (buf * 4224 + r * 132 + c4 * 4) * 4,
                 Wb + (size_t)(kt * 32 + r) * N + c4 * 4);
        }
    };

    prefA(0, 0); prefB(0, 0); cp_commit();

    for (int kt = 0; kt < 8; kt++) {
        if (kt < 7) { prefA(kt + 1, (kt + 1) & 1); prefB(kt + 1, (kt + 1) & 1); cp_commit(); }
        if (kt < 7) cp_wait<1>(); else cp_wait<0>();
        __syncthreads();
        const float* Asb = As + (kt & 1) * 4608;
        const float* Bsb = Bs + (kt & 1) * 4224;
#pragma unroll
        for (int kk = 0; kk < 4; kk++) {
            FragA af[2];
            FragBR bf[4];
#pragma unroll
            for (int mt = 0; mt < 2; mt++) {
                wmma::load_matrix_sync(af[mt], Asb + (wm * 32 + mt * 16) * 36 + kk * 8, 36);
                cvt_tf32(af[mt]);
            }
#pragma unroll
            for (int nt = 0; nt < 4; nt++) {
                wmma::load_matrix_sync(bf[nt], Bsb + (kk * 8) * 132 + wn * 64 + nt * 16, 132);
                cvt_tf32(bf[nt]);
            }
#pragma unroll
            for (int mt = 0; mt < 2; mt++)
#pragma unroll
                for (int nt = 0; nt < 4; nt++)
                    wmma::mma_sync(acc[mt][nt], af[mt], bf[nt], acc[mt][nt]);
        }
        __syncthreads();
    }

#pragma unroll
    for (int mt = 0; mt < 2; mt++)
#pragma unroll
        for (int nt = 0; nt < 4; nt++)
            wmma::store_matrix_sync(Cs + (wm * 32 + mt * 16) * 132 + wn * 64 + nt * 16,
                                    acc[mt][nt], 132, wmma::mem_row_major);
    __syncthreads();
#pragma unroll
    for (int it = 0; it < 64; it++) {
        int e = it * 256 + tid;
        int r = e >> 7, c = e & 127;
        C[((size_t)bm * 128 + r) * N + bn * 128 + c] = Cs[r * 132 + c] + bias[bn * 128 + c];
    }
}

// ---------------- flash attention: one CTA per (b,h), 512 threads -----------
// warp w owns q rows [16w, 16w+16); K/V streamed in 64-key chunks (cp.async x2)
// smem: K 2x64x36 | V 2x64x36 | per-warp scratch 16x(16x68) | O 256x36 |
//       mrow/srow/alpha 256 each   = 146432 B
__global__ void __launch_bounds__(512, 1) attn_kernel(const float* __restrict__ qp,
                                                      const float* __restrict__ kvp,
                                                      const float* __restrict__ bias_mat,
                                                      float* __restrict__ ao) {
    extern __shared__ float sm[];
    float* Ksm = sm;                         // 2 x 2304
    float* Vsm = Ksm + 2 * 2304;             // 2 x 2304
    float* Ssc = Vsm + 2 * 2304;             // 16 x 1088 (16x68 per warp)
    float* Osm = Ssc + 16 * 1088;            // 256 x 36
    float* mrow = Osm + 256 * 36;            // 256
    float* srow = mrow + 256;                // 256
    float* arow = srow + 256;                // 256

    const int bx = blockIdx.x;
    const int h = bx & 7, b = bx >> 3;
    const int tid = threadIdx.x, w = tid >> 5, lane = tid & 31;
    const int LDKV = 2 * DIMX;
    const int r0 = w * 16;

    const float* Kb = kvp + ((size_t)b * NK) * LDKV + h * DH;
    const float* Vb = Kb + DIMX;
    uint32_t sK = (uint32_t)__cvta_generic_to_shared(Ksm);
    uint32_t sV = (uint32_t)__cvta_generic_to_shared(Vsm);
    float* myS = Ssc + w * 1088;

    // prefetch KV chunk 0 (512 threads cover 64 rows x 8 float4 each of K,V)
    auto prefKV = [&](int chunk, int buf) {
        int r = tid >> 3, c4 = tid & 7;
        const float* src = Kb + (size_t)(chunk * 64 + r) * LDKV + c4 * 4;
        cp16(sK + (buf * 2304 + r * 36 + c4 * 4) * 4, src);
        cp16(sV + (buf * 2304 + r * 36 + c4 * 4) * 4, src + DIMX);
    };
    prefKV(0, 0); cp_commit();

    // init O, stats
    for (int i = tid; i < 256 * 36; i += 512) Osm[i] = 0.f;
    for (int i = tid; i < 256; i += 512) { mrow[i] = -1e30f; srow[i] = 0.f; }

    // stage Q rows into per-warp scratch, pull fragments to registers
    for (int i = lane; i < 128; i += 32) {   // 16 rows x 8 float4
        int r = i >> 3, c4 = i & 7;
        *(float4*)(myS + r * 68 + c4 * 4) =
            *(const float4*)(qp + ((size_t)(b * NQ + r0 + r)) * DIMX + h * DH + c4 * 4);
    }
    __syncwarp();
    FragA qf[4];
#pragma unroll
    for (int kk = 0; kk < 4; kk++) {
        wmma::load_matrix_sync(qf[kk], myS + kk * 8, 68);
        cvt_tf32(qf[kk]);
    }
    __syncthreads();

    const float* bm = bias_mat + (size_t)h * NQ * NK;

    for (int c = 0; c < 9; c++) {
        if (c < 8) { prefKV(c + 1, (c + 1) & 1); cp_commit(); }
        if (c < 8) cp_wait<1>(); else cp_wait<0>();
        __syncthreads();
        const float* Ks = Ksm + (c & 1) * 2304;
        const float* Vs = Vsm + (c & 1) * 2304;

        // ---- QK: S(16x64) = Q(16x32) @ K^T ----
        FragC acc[4];
#pragma unroll
        for (int nt = 0; nt < 4; nt++) wmma::fill_fragment(acc[nt], 0.f);
#pragma unroll
        for (int kk = 0; kk < 4; kk++) {
#pragma unroll
            for (int nt = 0; nt < 4; nt++) {
                FragBC bf;
                wmma::load_matrix_sync(bf, Ks + (nt * 16) * 36 + kk * 8, 36);
                cvt_tf32(bf);
                wmma::mma_sync(acc[nt], qf[kk], bf, acc[nt]);
            }
        }
        __syncwarp();
#pragma unroll
        for (int nt = 0; nt < 4; nt++)
            wmma::store_matrix_sync(myS + nt * 16, acc[nt], 68, wmma::mem_row_major);
        __syncwarp();

        // ---- online softmax on warp's 16x64 chunk ----
#pragma unroll
        for (int rr = 0; rr < 16; rr++) {
            int row = r0 + rr;
            float* srw = myS + rr * 68;
            const float* br = bm + (size_t)row * NK + c * 64;
            float v0 = srw[lane] * SCALE + br[lane];
            float v1 = srw[lane + 32] * SCALE + br[lane + 32];
            float cm = fmaxf(v0, v1);
#pragma unroll
            for (int o = 16; o; o >>= 1) cm = fmaxf(cm, __shfl_xor_sync(0xffffffffu, cm, o));
            float m_old = mrow[row];
            float m_new = fmaxf(m_old, cm);
            float p0 = __expf(v0 - m_new);
            float p1 = __expf(v1 - m_new);
            srw[lane] = p0;
            srw[lane + 32] = p1;
            float cs = p0 + p1;
#pragma unroll
            for (int o = 16; o; o >>= 1) cs += __shfl_xor_sync(0xffffffffu, cs, o);
            if (lane == 0) {
                float a = __expf(m_old - m_new);
                mrow[row] = m_new;
                srow[row] = srow[row] * a + cs;
                arow[row] = a;
            }
        }
        __syncwarp();

        // ---- PV: T(16x32) = P(16x64) @ V(64x32) ----
        FragC t0, t1;
        wmma::fill_fragment(t0, 0.f);
        wmma::fill_fragment(t1, 0.f);
#pragma unroll
        for (int kk = 0; kk < 8; kk++) {
            FragA pf;
            wmma::load_matrix_sync(pf, myS + kk * 8, 68);
            cvt_tf32(pf);
            FragBR vf0, vf1;
            wmma::load_matrix_sync(vf0, Vs + (kk * 8) * 36, 36);
            cvt_tf32(vf0);
            wmma::load_matrix_sync(vf1, Vs + (kk * 8) * 36 + 16, 36);
            cvt_tf32(vf1);
            wmma::mma_sync(t0, pf, vf0, t0);
            wmma::mma_sync(t1, pf, vf1, t1);
        }
        __syncwarp();
        wmma::store_matrix_sync(myS, t0, 68, wmma::mem_row_major);
        wmma::store_matrix_sync(myS + 16, t1, 68, wmma::mem_row_major);
        __syncwarp();

        // ---- merge into O with per-row rescale ----
#pragma unroll
        for (int k = 0; k < 16; k++) {
            int row = r0 + k;
            float a = arow[row];
            float* orow = Osm + row * 36;
            orow[lane] = orow[lane] * a + myS[k * 68 + lane];
        }
        __syncthreads();   // all warps done with this chunk's K/V buffers
    }

    // ---- normalize + write out [B, Nq, H*Dh] ----
    for (int i = tid; i < 256 * 32; i += 512) {
        int r = i >> 5, cc = i & 31;
        ao[((size_t)(b * NQ + r)) * DIMX + h * DH + cc] = Osm[r * 36 + cc] / srow[r];
    }
}

// ---------------- launch ----------------------------------------------------
extern "C" void kernel_launch(void* const* d_in, const int* in_sizes, int n_in,
                              void* d_out, int out_size) {
    const float* q_w = (const float*)d_in[0];
    const float* kv_w = (const float*)d_in[1];
    const float* q_W = (const float*)d_in[2];
    const float* q_b = (const float*)d_in[3];
    const float* kv_W = (const float*)d_in[4];
    const float* kv_b = (const float*)d_in[5];
    const float* proj_W = (const float*)d_in[6];
    const float* proj_b = (const float*)d_in[7];
    const float* bias_table = (const float*)d_in[8];
    const int* rel_index = (const int*)d_in[9];
    float* out = (float*)d_out;

    float *qp, *kvp, *bias, *ao;
    cudaGetSymbolAddress((void**)&qp, g_qp);
    cudaGetSymbolAddress((void**)&kvp, g_kvp);
    cudaGetSymbolAddress((void**)&bias, g_bias);
    cudaGetSymbolAddress((void**)&ao, g_ao);

    const int GEMM_SMEM = (2 * 128 * 36 + 2 * 32 * 132) * 4;                 // 70656 B
    const int ATTN_SMEM = (2 * 2304 + 2 * 2304 + 16 * 1088 + 256 * 36 + 3 * 256) * 4;  // 146432 B

    cudaFuncSetAttribute(gemm_tf32, cudaFuncAttributeMaxDynamicSharedMemorySize, GEMM_SMEM);
    cudaFuncSetAttribute(attn_kernel, cudaFuncAttributeMaxDynamicSharedMemorySize, ATTN_SMEM);

    bias_gather<<<(NQ * NK + 255) / 256, 256>>>(bias_table, rel_index, bias);
    gemm_tf32<<<dim3(2, 512), 256, GEMM_SMEM>>>(q_w, q_W, q_b, qp, 256);
    gemm_tf32<<<dim3(4, 1152), 256, GEMM_SMEM>>>(kv_w, kv_W, kv_b, kvp, 512);
    attn_kernel<<<BATCH * HEADS, 512, ATTN_SMEM>>>(qp, kvp, bias, ao);
    gemm_tf32<<<dim3(2, 512), 256, GEMM_SMEM>>>(ao, proj_W, proj_b, out, 256);
}

// round 6
// speedup vs baseline: 2.4509x; 1.7949x over previous
#include <cuda_runtime.h>
#include <cuda_fp16.h>
#include <cstdint>
#include <mma.h>

using namespace nvcuda;

#define DIMX   256
#define HEADS  8
#define BATCH  256
#define NQ     256
#define NK     576
#define DH     32
#define SCALE  0.17677669529663687f

// ---------------- scratch (device globals: no allocations allowed) ----------
__device__ __align__(16) __half g_qwh[(size_t)BATCH * NQ * DIMX];        // A of q-proj (half)
__device__ __align__(16) __half g_kvwh[(size_t)BATCH * NK * DIMX];       // A of kv-proj
__device__ __align__(16) __half g_wqh[DIMX * DIMX];
__device__ __align__(16) __half g_wkvh[DIMX * 2 * DIMX];
__device__ __align__(16) __half g_wph[DIMX * DIMX];
__device__ __align__(16) __half g_qph[(size_t)BATCH * NQ * DIMX];        // q projected
__device__ __align__(16) __half g_kvph[(size_t)BATCH * NK * 2 * DIMX];   // kv projected
__device__ __align__(16) __half g_biash[(size_t)HEADS * NQ * NK];        // bias [H,Nq,Nk]
__device__ __align__(16) __half g_aoh[(size_t)BATCH * NQ * DIMX];        // attn out

typedef wmma::fragment<wmma::matrix_a, 16, 16, 16, __half, wmma::row_major> HFragA;
typedef wmma::fragment<wmma::matrix_b, 16, 16, 16, __half, wmma::row_major> HFragBR;
typedef wmma::fragment<wmma::matrix_b, 16, 16, 16, __half, wmma::col_major> HFragBC;
typedef wmma::fragment<wmma::accumulator, 16, 16, 16, float> HFragC;

__device__ __forceinline__ void cp16(uint32_t dst, const void* src) {
    asm volatile("cp.async.cg.shared.global [%0], [%1], 16;\n" :: "r"(dst), "l"(src));
}
__device__ __forceinline__ void cp_commit() {
    asm volatile("cp.async.commit_group;\n");
}
template <int N>
__device__ __forceinline__ void cp_wait() {
    asm volatile("cp.async.wait_group %0;\n" :: "n"(N));
}

// ---------------- f32 -> f16 conversion ------------------------------------
__global__ void f2h(const float4* __restrict__ src, __half* __restrict__ dst, int n4) {
    int i = blockIdx.x * 256 + threadIdx.x;
    if (i >= n4) return;
    float4 v = src[i];
    __half2* d = (__half2*)dst;
    d[i * 2 + 0] = __floats2half2_rn(v.x, v.y);
    d[i * 2 + 1] = __floats2half2_rn(v.z, v.w);
}

// ---------------- gather relative-position bias -> half [H,Nq,Nk] ----------
__global__ void bias_gather(const float* __restrict__ table,
                            const int* __restrict__ rel,
                            __half* __restrict__ bias_mat) {
    int p = blockIdx.x * 256 + threadIdx.x;
    if (p >= NQ * NK) return;
    int idx = rel[p];
    const float4* t4 = reinterpret_cast<const float4*>(table + (size_t)idx * 8);
    float4 a = t4[0];
    float4 b = t4[1];
    const int PL = NQ * NK;
    bias_mat[0 * PL + p] = __float2half(a.x);
    bias_mat[1 * PL + p] = __float2half(a.y);
    bias_mat[2 * PL + p] = __float2half(a.z);
    bias_mat[3 * PL + p] = __float2half(a.w);
    bias_mat[4 * PL + p] = __float2half(b.x);
    bias_mat[5 * PL + p] = __float2half(b.y);
    bias_mat[6 * PL + p] = __float2half(b.z);
    bias_mat[7 * PL + p] = __float2half(b.w);
}

// ---------------- fp16 GEMM: C[M,N] = A[M,256] @ W[256,N] + bias ------------
// block 128x128, BK=32, 8 warps (4x2), warp tile 32x64 (2x4 k16 frags)
// smem: A 2x128x40 half, B 2x32x136 half; epilogue reuses as 128x132 f32
template <int OUT_HALF>
__global__ void __launch_bounds__(256, 2) gemm_h(const __half* __restrict__ A,
                                                 const __half* __restrict__ W,
                                                 const float* __restrict__ bias,
                                                 void* __restrict__ Cv, int N) {
    extern __shared__ char smraw[];
    __half* As = (__half*)smraw;          // 2 x 128 x 40
    __half* Bs = As + 2 * 128 * 40;       // 2 x 32 x 136
    float* Cs = (float*)smraw;            // 128 x 132

    const int tid = threadIdx.x;
    const int w = tid >> 5;
    const int wm = w >> 1;
    const int wn = w & 1;
    const int bm = blockIdx.y, bn = blockIdx.x;

    const __half* Ab = A + (size_t)bm * 128 * 256;
    const __half* Wb = W + bn * 128;

    uint32_t sA = (uint32_t)__cvta_generic_to_shared(As);
    uint32_t sB = (uint32_t)__cvta_generic_to_shared(Bs);

    HFragC acc[2][4];
#pragma unroll
    for (int mt = 0; mt < 2; mt++)
#pragma unroll
        for (int nt = 0; nt < 4; nt++) wmma::fill_fragment(acc[mt][nt], 0.f);

    auto prefA = [&](int kt, int buf) {
#pragma unroll
        for (int it = 0; it < 2; it++) {
            int i = it * 256 + tid;           // 512 chunks of 8 halves
            int r = i >> 2, c8 = i & 3;
            cp16(sA + (buf * 5120 + r * 40 + c8 * 8) * 2,
                 Ab + (size_t)r * 256 + kt * 32 + c8 * 8);
        }
    };
    auto prefB = [&](int kt, int buf) {
#pragma unroll
        for (int it = 0; it < 2; it++) {
            int i = it * 256 + tid;           // 512 chunks
            int r = i >> 4, c8 = i & 15;
            cp16(sB + (buf * 4352 + r * 136 + c8 * 8) * 2,
                 Wb + (size_t)(kt * 32 + r) * N + c8 * 8);
        }
    };

    prefA(0, 0); prefB(0, 0); cp_commit();

    for (int kt = 0; kt < 8; kt++) {
        if (kt < 7) { prefA(kt + 1, (kt + 1) & 1); prefB(kt + 1, (kt + 1) & 1); cp_commit(); }
        if (kt < 7) cp_wait<1>(); else cp_wait<0>();
        __syncthreads();
        const __half* Asb = As + (kt & 1) * 5120;
        const __half* Bsb = Bs + (kt & 1) * 4352;
#pragma unroll
        for (int kk = 0; kk < 2; kk++) {
            HFragA af[2];
            HFragBR bf[4];
#pragma unroll
            for (int mt = 0; mt < 2; mt++)
                wmma::load_matrix_sync(af[mt], Asb + (wm * 32 + mt * 16) * 40 + kk * 16, 40);
#pragma unroll
            for (int nt = 0; nt < 4; nt++)
                wmma::load_matrix_sync(bf[nt], Bsb + (kk * 16) * 136 + wn * 64 + nt * 16, 136);
#pragma unroll
            for (int mt = 0; mt < 2; mt++)
#pragma unroll
                for (int nt = 0; nt < 4; nt++)
                    wmma::mma_sync(acc[mt][nt], af[mt], bf[nt], acc[mt][nt]);
        }
        __syncthreads();
    }

    // epilogue: stage f32 to smem, add bias, write coalesced
#pragma unroll
    for (int mt = 0; mt < 2; mt++)
#pragma unroll
        for (int nt = 0; nt < 4; nt++)
            wmma::store_matrix_sync(Cs + (wm * 32 + mt * 16) * 132 + wn * 64 + nt * 16,
                                    acc[mt][nt], 132, wmma::mem_row_major);
    __syncthreads();
#pragma unroll
    for (int it = 0; it < 64; it++) {
        int e = it * 256 + tid;
        int r = e >> 7, c = e & 127;
        float v = Cs[r * 132 + c] + bias[bn * 128 + c];
        size_t off = ((size_t)bm * 128 + r) * N + bn * 128 + c;
        if (OUT_HALF) ((__half*)Cv)[off] = __float2half(v);
        else          ((float*)Cv)[off] = v;
    }
}

// ---------------- flash attention (fp16 operands): one CTA per (b,h) --------
// 512 threads, warp w owns q rows [16w,16w+16); K/V streamed 64-key chunks
__global__ void __launch_bounds__(512, 1) attn_kernel(const __half* __restrict__ qp,
                                                      const __half* __restrict__ kvp,
                                                      const __half* __restrict__ bias_mat,
                                                      __half* __restrict__ ao) {
    extern __shared__ char smraw[];
    __half* Ksm = (__half*)smraw;            // 2 x 64 x 40
    __half* Vsm = Ksm + 2 * 2560;            // 2 x 64 x 40
    float* Ssc = (float*)(Vsm + 2 * 2560);   // 16 warps x 16 x 68 f32
    float* Osm = Ssc + 16 * 1088;            // 256 x 36
    float* mrow = Osm + 256 * 36;            // 256
    float* srow = mrow + 256;                // 256
    float* arow = srow + 256;                // 256

    const int bx = blockIdx.x;
    const int h = bx & 7, b = bx >> 3;
    const int tid = threadIdx.x, w = tid >> 5, lane = tid & 31;
    const int LDKV = 2 * DIMX;               // halves
    const int r0 = w * 16;

    const __half* Kb = kvp + ((size_t)b * NK) * LDKV + h * DH;
    const __half* Vb = Kb + DIMX;
    uint32_t sK = (uint32_t)__cvta_generic_to_shared(Ksm);
    uint32_t sV = (uint32_t)__cvta_generic_to_shared(Vsm);
    float* myS = Ssc + w * 1088;             // 16 x 68 f32 scratch
    __half* myH = (__half*)myS;              // half view: ld 136

    // 512 threads: lower half loads K chunk, upper half loads V chunk
    auto prefKV = [&](int chunk, int buf) {
        int t = tid & 255;
        int r = t >> 2, c8 = t & 3;          // 64 rows x 4 chunks of 8 halves
        const __half* src = ((tid < 256) ? Kb : Vb) + (size_t)(chunk * 64 + r) * LDKV + c8 * 8;
        uint32_t dst = ((tid < 256) ? sK : sV) + (buf * 2560 + r * 40 + c8 * 8) * 2;
        cp16(dst, src);
    };
    prefKV(0, 0); cp_commit();

    // init O, stats
    for (int i = tid; i < 256 * 36; i += 512) Osm[i] = 0.f;
    for (int i = tid; i < 256; i += 512) { mrow[i] = -1e30f; srow[i] = 0.f; }

    // stage warp's Q (16x32 half, ld 40) into scratch; pull frags to regs
    for (int i = lane; i < 64; i += 32) {    // 16 rows x 4 chunks of 16B
        int r = i >> 2, c8 = i & 3;
        *(uint4*)(myH + r * 40 + c8 * 8) =
            *(const uint4*)(qp + ((size_t)(b * NQ + r0 + r)) * DIMX + h * DH + c8 * 8);
    }
    __syncwarp();
    HFragA qf[2];
#pragma unroll
    for (int kk = 0; kk < 2; kk++)
        wmma::load_matrix_sync(qf[kk], myH + kk * 16, 40);
    __syncthreads();

    const __half* bm = bias_mat + (size_t)h * NQ * NK;

    for (int c = 0; c < 9; c++) {
        if (c < 8) { prefKV(c + 1, (c + 1) & 1); cp_commit(); }
        if (c < 8) cp_wait<1>(); else cp_wait<0>();
        __syncthreads();
        const __half* Ks = Ksm + (c & 1) * 2560;
        const __half* Vs = Vsm + (c & 1) * 2560;

        // ---- QK: S(16x64) = Q(16x32) @ K^T ----
        HFragC acc[4];
#pragma unroll
        for (int nt = 0; nt < 4; nt++) wmma::fill_fragment(acc[nt], 0.f);
#pragma unroll
        for (int kk = 0; kk < 2; kk++) {
#pragma unroll
            for (int nt = 0; nt < 4; nt++) {
                HFragBC bf;
                wmma::load_matrix_sync(bf, Ks + (nt * 16) * 40 + kk * 16, 40);
                wmma::mma_sync(acc[nt], qf[kk], bf, acc[nt]);
            }
        }
        __syncwarp();
#pragma unroll
        for (int nt = 0; nt < 4; nt++)
            wmma::store_matrix_sync(myS + nt * 16, acc[nt], 68, wmma::mem_row_major);
        __syncwarp();

        // ---- online softmax; write P as half in-place over f32 rows ----
#pragma unroll
        for (int rr = 0; rr < 16; rr++) {
            int row = r0 + rr;
            float* srw = myS + rr * 68;
            const __half* br = bm + (size_t)row * NK + c * 64;
            float v0 = fmaf(srw[lane], SCALE, __half2float(br[lane]));
            float v1 = fmaf(srw[lane + 32], SCALE, __half2float(br[lane + 32]));
            float cm = fmaxf(v0, v1);
#pragma unroll
            for (int o = 16; o; o >>= 1) cm = fmaxf(cm, __shfl_xor_sync(0xffffffffu, cm, o));
            float m_old = mrow[row];
            float m_new = fmaxf(m_old, cm);
            float p0 = __expf(v0 - m_new);
            float p1 = __expf(v1 - m_new);
            __half* hrow = myH + rr * 136;   // overlays f32 slots [0,32) of this row
            hrow[lane] = __float2half(p0);
            hrow[lane + 32] = __float2half(p1);
            float cs = p0 + p1;
#pragma unroll
            for (int o = 16; o; o >>= 1) cs += __shfl_xor_sync(0xffffffffu, cs, o);
            if (lane == 0) {
                float a = __expf(m_old - m_new);
                mrow[row] = m_new;
                srow[row] = srow[row] * a + cs;
                arow[row] = a;
            }
        }
        __syncwarp();

        // ---- PV: T(16x32) = P(16x64) @ V(64x32) ----
        HFragC t0, t1;
        wmma::fill_fragment(t0, 0.f);
        wmma::fill_fragment(t1, 0.f);
#pragma unroll
        for (int kk = 0; kk < 4; kk++) {
            HFragA pf;
            wmma::load_matrix_sync(pf, myH + kk * 16, 136);
            HFragBR vf0, vf1;
            wmma::load_matrix_sync(vf0, Vs + (kk * 16) * 40, 40);
            wmma::load_matrix_sync(vf1, Vs + (kk * 16) * 40 + 16, 40);
            wmma::mma_sync(t0, pf, vf0, t0);
            wmma::mma_sync(t1, pf, vf1, t1);
        }
        __syncwarp();
        wmma::store_matrix_sync(myS, t0, 68, wmma::mem_row_major);
        wmma::store_matrix_sync(myS + 16, t1, 68, wmma::mem_row_major);
        __syncwarp();

        // ---- merge into O with per-row rescale ----
#pragma unroll
        for (int k = 0; k < 16; k++) {
            int row = r0 + k;
            float a = arow[row];
            float* orow = Osm + row * 36;
            orow[lane] = orow[lane] * a + myS[k * 68 + lane];
        }
        __syncthreads();
    }

    // ---- normalize + write out (half) [B, Nq, H*Dh] ----
    for (int i = tid; i < 256 * 32; i += 512) {
        int r = i >> 5, cc = i & 31;
        ao[((size_t)(b * NQ + r)) * DIMX + h * DH + cc] =
            __float2half(Osm[r * 36 + cc] / srow[r]);
    }
}

// ---------------- launch ----------------------------------------------------
extern "C" void kernel_launch(void* const* d_in, const int* in_sizes, int n_in,
                              void* d_out, int out_size) {
    const float* q_w = (const float*)d_in[0];
    const float* kv_w = (const float*)d_in[1];
    const float* q_W = (const float*)d_in[2];
    const float* q_b = (const float*)d_in[3];
    const float* kv_W = (const float*)d_in[4];
    const float* kv_b = (const float*)d_in[5];
    const float* proj_W = (const float*)d_in[6];
    const float* proj_b = (const float*)d_in[7];
    const float* bias_table = (const float*)d_in[8];
    const int* rel_index = (const int*)d_in[9];
    float* out = (float*)d_out;

    __half *qwh, *kvwh, *wqh, *wkvh, *wph, *qph, *kvph, *biash, *aoh;
    cudaGetSymbolAddress((void**)&qwh, g_qwh);
    cudaGetSymbolAddress((void**)&kvwh, g_kvwh);
    cudaGetSymbolAddress((void**)&wqh, g_wqh);
    cudaGetSymbolAddress((void**)&wkvh, g_wkvh);
    cudaGetSymbolAddress((void**)&wph, g_wph);
    cudaGetSymbolAddress((void**)&qph, g_qph);
    cudaGetSymbolAddress((void**)&kvph, g_kvph);
    cudaGetSymbolAddress((void**)&biash, g_biash);
    cudaGetSymbolAddress((void**)&aoh, g_aoh);

    const int GEMM_SMEM = 128 * 132 * 4;                                  // 67584 B
    const int ATTN_SMEM = (2 * 2560 + 2 * 2560) * 2 + (16 * 1088 + 256 * 36 + 3 * 256) * 4;  // 130048 B

    cudaFuncSetAttribute(gemm_h<1>, cudaFuncAttributeMaxDynamicSharedMemorySize, GEMM_SMEM);
    cudaFuncSetAttribute(gemm_h<0>, cudaFuncAttributeMaxDynamicSharedMemorySize, GEMM_SMEM);
    cudaFuncSetAttribute(attn_kernel, cudaFuncAttributeMaxDynamicSharedMemorySize, ATTN_SMEM);

    // f32 -> f16 conversions
    f2h<<<(4194304 + 255) / 256, 256>>>((const float4*)q_w, qwh, 4194304);
    f2h<<<(9437184 + 255) / 256, 256>>>((const float4*)kv_w, kvwh, 9437184);
    f2h<<<(16384 + 255) / 256, 256>>>((const float4*)q_W, wqh, 16384);
    f2h<<<(32768 + 255) / 256, 256>>>((const float4*)kv_W, wkvh, 32768);
    f2h<<<(16384 + 255) / 256, 256>>>((const float4*)proj_W, wph, 16384);
    bias_gather<<<(NQ * NK + 255) / 256, 256>>>(bias_table, rel_index, biash);

    gemm_h<1><<<dim3(2, 512), 256, GEMM_SMEM>>>(qwh, wqh, q_b, qph, 256);
    gemm_h<1><<<dim3(4, 1152), 256, GEMM_SMEM>>>(kvwh, wkvh, kv_b, kvph, 512);
    attn_kernel<<<BATCH * HEADS, 512, ATTN_SMEM>>>(qph, kvph, biash, aoh);
    gemm_h<0><<<dim3(2, 512), 256, GEMM_SMEM>>>(aoh, wph, proj_b, out, 256);
}

// round 7
// speedup vs baseline: 4.1594x; 1.6971x over previous
#include <cuda_runtime.h>
#include <cuda_fp16.h>
#include <cstdint>
#include <mma.h>

using namespace nvcuda;

#define DIMX   256
#define HEADS  8
#define BATCH  256
#define NQ     256
#define NK     576
#define DH     32
#define SCALE  0.17677669529663687f

// ---------------- scratch (device globals: no allocations allowed) ----------
__device__ __align__(16) __half g_qwh[(size_t)BATCH * NQ * DIMX];
__device__ __align__(16) __half g_kvwh[(size_t)BATCH * NK * DIMX];
__device__ __align__(16) __half g_wqh[DIMX * DIMX];
__device__ __align__(16) __half g_wkvh[DIMX * 2 * DIMX];
__device__ __align__(16) __half g_wph[DIMX * DIMX];
__device__ __align__(16) __half g_qph[(size_t)BATCH * NQ * DIMX];
__device__ __align__(16) __half g_kvph[(size_t)BATCH * NK * 2 * DIMX];
__device__ __align__(16) __half g_biash[(size_t)HEADS * NQ * NK];
__device__ __align__(16) __half g_aoh[(size_t)BATCH * NQ * DIMX];

typedef wmma::fragment<wmma::matrix_a, 16, 16, 16, __half, wmma::row_major> HFragA;
typedef wmma::fragment<wmma::matrix_b, 16, 16, 16, __half, wmma::row_major> HFragBR;
typedef wmma::fragment<wmma::accumulator, 16, 16, 16, float> HFragC;

__device__ __forceinline__ void cp16(uint32_t dst, const void* src) {
    asm volatile("cp.async.cg.shared.global [%0], [%1], 16;\n" :: "r"(dst), "l"(src));
}
__device__ __forceinline__ void cp_commit() {
    asm volatile("cp.async.commit_group;\n");
}
template <int N>
__device__ __forceinline__ void cp_wait() {
    asm volatile("cp.async.wait_group %0;\n" :: "n"(N));
}

__device__ __forceinline__ void ldsm4(uint32_t addr, uint32_t& r0, uint32_t& r1,
                                      uint32_t& r2, uint32_t& r3) {
    asm volatile("ldmatrix.sync.aligned.m8n8.x4.shared.b16 {%0,%1,%2,%3}, [%4];"
                 : "=r"(r0), "=r"(r1), "=r"(r2), "=r"(r3) : "r"(addr));
}
__device__ __forceinline__ void ldsm4t(uint32_t addr, uint32_t& r0, uint32_t& r1,
                                       uint32_t& r2, uint32_t& r3) {
    asm volatile("ldmatrix.sync.aligned.m8n8.x4.trans.shared.b16 {%0,%1,%2,%3}, [%4];"
                 : "=r"(r0), "=r"(r1), "=r"(r2), "=r"(r3) : "r"(addr));
}
__device__ __forceinline__ void mma16816(float* c, uint32_t a0, uint32_t a1, uint32_t a2,
                                         uint32_t a3, uint32_t b0, uint32_t b1) {
    asm volatile(
        "mma.sync.aligned.m16n8k16.row.col.f32.f16.f16.f32 "
        "{%0,%1,%2,%3},{%4,%5,%6,%7},{%8,%9},{%0,%1,%2,%3};"
        : "+f"(c[0]), "+f"(c[1]), "+f"(c[2]), "+f"(c[3])
        : "r"(a0), "r"(a1), "r"(a2), "r"(a3), "r"(b0), "r"(b1));
}
__device__ __forceinline__ uint32_t h2pack(float lo, float hi) {
    __half2 h = __floats2half2_rn(lo, hi);
    return *reinterpret_cast<uint32_t*>(&h);
}

// ---------------- f32 -> f16 conversion ------------------------------------
__global__ void f2h(const float4* __restrict__ src, __half* __restrict__ dst, int n4) {
    int i = blockIdx.x * 256 + threadIdx.x;
    if (i >= n4) return;
    float4 v = src[i];
    __half2* d = (__half2*)dst;
    d[i * 2 + 0] = __floats2half2_rn(v.x, v.y);
    d[i * 2 + 1] = __floats2half2_rn(v.z, v.w);
}

// ---------------- gather relative-position bias -> half [H,Nq,Nk] ----------
__global__ void bias_gather(const float* __restrict__ table,
                            const int* __restrict__ rel,
                            __half* __restrict__ bias_mat) {
    int p = blockIdx.x * 256 + threadIdx.x;
    if (p >= NQ * NK) return;
    int idx = rel[p];
    const float4* t4 = reinterpret_cast<const float4*>(table + (size_t)idx * 8);
    float4 a = t4[0];
    float4 b = t4[1];
    const int PL = NQ * NK;
    bias_mat[0 * PL + p] = __float2half(a.x);
    bias_mat[1 * PL + p] = __float2half(a.y);
    bias_mat[2 * PL + p] = __float2half(a.z);
    bias_mat[3 * PL + p] = __float2half(a.w);
    bias_mat[4 * PL + p] = __float2half(b.x);
    bias_mat[5 * PL + p] = __float2half(b.y);
    bias_mat[6 * PL + p] = __float2half(b.z);
    bias_mat[7 * PL + p] = __float2half(b.w);
}

// ---------------- fp16 GEMM (unchanged from R6) -----------------------------
template <int OUT_HALF>
__global__ void __launch_bounds__(256, 2) gemm_h(const __half* __restrict__ A,
                                                 const __half* __restrict__ W,
                                                 const float* __restrict__ bias,
                                                 void* __restrict__ Cv, int N) {
    extern __shared__ char smraw[];
    __half* As = (__half*)smraw;          // 2 x 128 x 40
    __half* Bs = As + 2 * 128 * 40;       // 2 x 32 x 136
    float* Cs = (float*)smraw;            // 128 x 132

    const int tid = threadIdx.x;
    const int w = tid >> 5;
    const int wm = w >> 1;
    const int wn = w & 1;
    const int bm = blockIdx.y, bn = blockIdx.x;

    const __half* Ab = A + (size_t)bm * 128 * 256;
    const __half* Wb = W + bn * 128;

    uint32_t sA = (uint32_t)__cvta_generic_to_shared(As);
    uint32_t sB = (uint32_t)__cvta_generic_to_shared(Bs);

    HFragC acc[2][4];
#pragma unroll
    for (int mt = 0; mt < 2; mt++)
#pragma unroll
        for (int nt = 0; nt < 4; nt++) wmma::fill_fragment(acc[mt][nt], 0.f);

    auto prefA = [&](int kt, int buf) {
#pragma unroll
        for (int it = 0; it < 2; it++) {
            int i = it * 256 + tid;
            int r = i >> 2, c8 = i & 3;
            cp16(sA + (buf * 5120 + r * 40 + c8 * 8) * 2,
                 Ab + (size_t)r * 256 + kt * 32 + c8 * 8);
        }
    };
    auto prefB = [&](int kt, int buf) {
#pragma unroll
        for (int it = 0; it < 2; it++) {
            int i = it * 256 + tid;
            int r = i >> 4, c8 = i & 15;
            cp16(sB + (buf * 4352 + r * 136 + c8 * 8) * 2,
                 Wb + (size_t)(kt * 32 + r) * N + c8 * 8);
        }
    };

    prefA(0, 0); prefB(0, 0); cp_commit();

    for (int kt = 0; kt < 8; kt++) {
        if (kt < 7) { prefA(kt + 1, (kt + 1) & 1); prefB(kt + 1, (kt + 1) & 1); cp_commit(); }
        if (kt < 7) cp_wait<1>(); else cp_wait<0>();
        __syncthreads();
        const __half* Asb = As + (kt & 1) * 5120;
        const __half* Bsb = Bs + (kt & 1) * 4352;
#pragma unroll
        for (int kk = 0; kk < 2; kk++) {
            HFragA af[2];
            HFragBR bf[4];
#pragma unroll
            for (int mt = 0; mt < 2; mt++)
                wmma::load_matrix_sync(af[mt], Asb + (wm * 32 + mt * 16) * 40 + kk * 16, 40);
#pragma unroll
            for (int nt = 0; nt < 4; nt++)
                wmma::load_matrix_sync(bf[nt], Bsb + (kk * 16) * 136 + wn * 64 + nt * 16, 136);
#pragma unroll
            for (int mt = 0; mt < 2; mt++)
#pragma unroll
                for (int nt = 0; nt < 4; nt++)
                    wmma::mma_sync(acc[mt][nt], af[mt], bf[nt], acc[mt][nt]);
        }
        __syncthreads();
    }

#pragma unroll
    for (int mt = 0; mt < 2; mt++)
#pragma unroll
        for (int nt = 0; nt < 4; nt++)
            wmma::store_matrix_sync(Cs + (wm * 32 + mt * 16) * 132 + wn * 64 + nt * 16,
                                    acc[mt][nt], 132, wmma::mem_row_major);
    __syncthreads();
#pragma unroll
    for (int it = 0; it < 64; it++) {
        int e = it * 256 + tid;
        int r = e >> 7, c = e & 127;
        float v = Cs[r * 132 + c] + bias[bn * 128 + c];
        size_t off = ((size_t)bm * 128 + r) * N + bn * 128 + c;
        if (OUT_HALF) ((__half*)Cv)[off] = __float2half(v);
        else          ((float*)Cv)[off] = v;
    }
}

// ---------------- flash attention v3: raw mma PTX, register-resident --------
// one CTA per (b,h), 512 threads, warp w owns q rows [16w,16w+16)
// smem: K 2x64x40h | V 2x64x40h | Ostage 256x40h  = 40960 B
__global__ void __launch_bounds__(512, 1) attn_kernel(const __half* __restrict__ qp,
                                                      const __half* __restrict__ kvp,
                                                      const __half* __restrict__ bias_mat,
                                                      __half* __restrict__ ao) {
    extern __shared__ char smraw[];
    __half* Ksm = (__half*)smraw;            // 2 x 64 x 40
    __half* Vsm = Ksm + 2 * 2560;            // 2 x 64 x 40
    __half* Ost = Vsm + 2 * 2560;            // 256 x 40 (Q staging + O staging)

    const int bx = blockIdx.x;
    const int h = bx & 7, b = bx >> 3;
    const int tid = threadIdx.x, w = tid >> 5, lane = tid & 31;
    const int LDKV = 2 * DIMX;
    const int q0 = w * 16;

    const __half* Kb = kvp + ((size_t)b * NK) * LDKV + h * DH;
    const __half* Vb = Kb + DIMX;
    const uint32_t sK = (uint32_t)__cvta_generic_to_shared(Ksm);
    const uint32_t sV = (uint32_t)__cvta_generic_to_shared(Vsm);
    const uint32_t sO = (uint32_t)__cvta_generic_to_shared(Ost);

    // cp.async: lower 256 threads load K chunk, upper 256 load V chunk
    auto prefKV = [&](int chunk, int buf) {
        int t = tid & 255;
        int r = t >> 2, c8 = t & 3;
        const __half* src = ((tid < 256) ? Kb : Vb) + (size_t)(chunk * 64 + r) * LDKV + c8 * 8;
        uint32_t dst = ((tid < 256) ? sK : sV) + (buf * 2560 + r * 40 + c8 * 8) * 2;
        cp16(dst, src);
    };
    prefKV(0, 0); cp_commit();

    // stage warp's Q (16 rows x 32 halves) into its Ost region, ldsm to A frags
    {
        const __half* qsrc = qp + ((size_t)(b * NQ + q0)) * DIMX + h * DH;
#pragma unroll
        for (int i = lane; i < 64; i += 32) {      // 16 rows x 4 uint4
            int r = i >> 2, c8 = i & 3;
            *(uint4*)(Ost + (q0 + r) * 40 + c8 * 8) =
                *(const uint4*)(qsrc + (size_t)r * DIMX + c8 * 8);
        }
        __syncwarp();
    }
    uint32_t qa[2][4];
    {
        int t = lane >> 3, wi = lane & 7;
        int qrow = q0 + (t & 1) * 8 + wi;
        int qcolbase = (t >> 1) * 8;
#pragma unroll
        for (int kt = 0; kt < 2; kt++)
            ldsm4(sO + (qrow * 40 + qcolbase + kt * 16) * 2,
                  qa[kt][0], qa[kt][1], qa[kt][2], qa[kt][3]);
    }

    // per-thread running stats for its two rows (r1 = q0+lane>>2, r2 = r1+8)
    const int r1 = q0 + (lane >> 2);
    const int r2 = r1 + 8;
    float m1 = -1e30f, m2 = -1e30f, s1 = 0.f, s2 = 0.f;
    float o[4][4];
#pragma unroll
    for (int j = 0; j < 4; j++)
#pragma unroll
        for (int e = 0; e < 4; e++) o[j][e] = 0.f;

    const __half* bm = bias_mat + (size_t)h * NQ * NK;
    const __half* b1base = bm + (size_t)r1 * NK + (lane & 3) * 2;
    const __half* b2base = bm + (size_t)r2 * NK + (lane & 3) * 2;

    // precomputed ldsm lane-address offsets
    const int kt_t = lane >> 3, kt_wi = lane & 7;
    const int krow_off = (kt_t >> 1) * 8 + kt_wi;      // key row within 16-group (K)
    const int kcol_off = (kt_t & 1) * 8;               // k-dim col offset (K)
    const int vrow_off = (kt_t & 1) * 8 + kt_wi;       // key row within 16-group (V)
    const int vcol_off = (kt_t >> 1) * 8;              // dim col offset (V)

    for (int c = 0; c < 9; c++) {
        cp_wait<0>();
        __syncthreads();
        if (c < 8) { prefKV(c + 1, (c + 1) & 1); cp_commit(); }

        const uint32_t sKc = sK + ((c & 1) * 2560) * 2;
        const uint32_t sVc = sV + ((c & 1) * 2560) * 2;

        // ---- QK: S(16x64), 8 n-tiles of m16n8 ----
        float s[8][4];
#pragma unroll
        for (int j = 0; j < 8; j++)
#pragma unroll
            for (int e = 0; e < 4; e++) s[j][e] = 0.f;

#pragma unroll
        for (int g = 0; g < 4; g++) {              // 16-key groups
#pragma unroll
            for (int kt = 0; kt < 2; kt++) {       // k-dim tiles
                uint32_t b0, b1, b2, b3;
                ldsm4(sKc + ((g * 16 + krow_off) * 40 + kt * 16 + kcol_off) * 2,
                      b0, b1, b2, b3);
                mma16816(s[2 * g],     qa[kt][0], qa[kt][1], qa[kt][2], qa[kt][3], b0, b1);
                mma16816(s[2 * g + 1], qa[kt][0], qa[kt][1], qa[kt][2], qa[kt][3], b2, b3);
            }
        }

        // ---- bias + scale + in-register online softmax ----
        const __half* b1p = b1base + c * 64;
        const __half* b2p = b2base + c * 64;
        float cm1 = -1e30f, cm2 = -1e30f;
#pragma unroll
        for (int j = 0; j < 8; j++) {
            __half2 bb1 = *(const __half2*)(b1p + j * 8);
            __half2 bb2 = *(const __half2*)(b2p + j * 8);
            s[j][0] = fmaf(s[j][0], SCALE, __low2float(bb1));
            s[j][1] = fmaf(s[j][1], SCALE, __high2float(bb1));
            s[j][2] = fmaf(s[j][2], SCALE, __low2float(bb2));
            s[j][3] = fmaf(s[j][3], SCALE, __high2float(bb2));
            cm1 = fmaxf(cm1, fmaxf(s[j][0], s[j][1]));
            cm2 = fmaxf(cm2, fmaxf(s[j][2], s[j][3]));
        }
        cm1 = fmaxf(cm1, __shfl_xor_sync(0xffffffffu, cm1, 1));
        cm1 = fmaxf(cm1, __shfl_xor_sync(0xffffffffu, cm1, 2));
        cm2 = fmaxf(cm2, __shfl_xor_sync(0xffffffffu, cm2, 1));
        cm2 = fmaxf(cm2, __shfl_xor_sync(0xffffffffu, cm2, 2));

        float m1n = fmaxf(m1, cm1), m2n = fmaxf(m2, cm2);
        float a1 = __expf(m1 - m1n), a2 = __expf(m2 - m2n);
        float sum1 = 0.f, sum2 = 0.f;
#pragma unroll
        for (int j = 0; j < 8; j++) {
            s[j][0] = __expf(s[j][0] - m1n);
            s[j][1] = __expf(s[j][1] - m1n);
            s[j][2] = __expf(s[j][2] - m2n);
            s[j][3] = __expf(s[j][3] - m2n);
            sum1 += s[j][0] + s[j][1];
            sum2 += s[j][2] + s[j][3];
        }
        sum1 += __shfl_xor_sync(0xffffffffu, sum1, 1);
        sum1 += __shfl_xor_sync(0xffffffffu, sum1, 2);
        sum2 += __shfl_xor_sync(0xffffffffu, sum2, 1);
        sum2 += __shfl_xor_sync(0xffffffffu, sum2, 2);
        s1 = s1 * a1 + sum1;
        s2 = s2 * a2 + sum2;
        m1 = m1n;
        m2 = m2n;

        // rescale O in-register
#pragma unroll
        for (int j = 0; j < 4; j++) {
            o[j][0] *= a1; o[j][1] *= a1;
            o[j][2] *= a2; o[j][3] *= a2;
        }

        // ---- PV: P (packed from S regs) @ V(64x32) ----
#pragma unroll
        for (int kt = 0; kt < 4; kt++) {           // 16-key k-tiles
            uint32_t pa0 = h2pack(s[2 * kt][0], s[2 * kt][1]);
            uint32_t pa1 = h2pack(s[2 * kt][2], s[2 * kt][3]);
            uint32_t pa2 = h2pack(s[2 * kt + 1][0], s[2 * kt + 1][1]);
            uint32_t pa3 = h2pack(s[2 * kt + 1][2], s[2 * kt + 1][3]);
#pragma unroll
            for (int vg = 0; vg < 2; vg++) {       // 16-dim n-groups
                uint32_t b0, b1, b2, b3;
                ldsm4t(sVc + ((kt * 16 + vrow_off) * 40 + vg * 16 + vcol_off) * 2,
                       b0, b1, b2, b3);
                mma16816(o[vg * 2],     pa0, pa1, pa2, pa3, b0, b1);
                mma16816(o[vg * 2 + 1], pa0, pa1, pa2, pa3, b2, b3);
            }
        }
        __syncthreads();   // all warps done with this chunk's buffers
    }

    // ---- normalize, stage to smem, coalesced store ----
    float inv1 = 1.f / s1, inv2 = 1.f / s2;
#pragma unroll
    for (int j = 0; j < 4; j++) {
        *(__half2*)(Ost + r1 * 40 + j * 8 + (lane & 3) * 2) =
            __floats2half2_rn(o[j][0] * inv1, o[j][1] * inv1);
        *(__half2*)(Ost + r2 * 40 + j * 8 + (lane & 3) * 2) =
            __floats2half2_rn(o[j][2] * inv2, o[j][3] * inv2);
    }
    __syncthreads();
    {
        int row = tid >> 1, seg = tid & 1;
        uint4* dst = (uint4*)(ao + ((size_t)(b * NQ + row)) * DIMX + h * DH + seg * 16);
        dst[0] = *(uint4*)(Ost + row * 40 + seg * 16);
        dst[1] = *(uint4*)(Ost + row * 40 + seg * 16 + 8);
    }
}

// ---------------- launch ----------------------------------------------------
extern "C" void kernel_launch(void* const* d_in, const int* in_sizes, int n_in,
                              void* d_out, int out_size) {
    const float* q_w = (const float*)d_in[0];
    const float* kv_w = (const float*)d_in[1];
    const float* q_W = (const float*)d_in[2];
    const float* q_b = (const float*)d_in[3];
    const float* kv_W = (const float*)d_in[4];
    const float* kv_b = (const float*)d_in[5];
    const float* proj_W = (const float*)d_in[6];
    const float* proj_b = (const float*)d_in[7];
    const float* bias_table = (const float*)d_in[8];
    const int* rel_index = (const int*)d_in[9];
    float* out = (float*)d_out;

    __half *qwh, *kvwh, *wqh, *wkvh, *wph, *qph, *kvph, *biash, *aoh;
    cudaGetSymbolAddress((void**)&qwh, g_qwh);
    cudaGetSymbolAddress((void**)&kvwh, g_kvwh);
    cudaGetSymbolAddress((void**)&wqh, g_wqh);
    cudaGetSymbolAddress((void**)&wkvh, g_wkvh);
    cudaGetSymbolAddress((void**)&wph, g_wph);
    cudaGetSymbolAddress((void**)&qph, g_qph);
    cudaGetSymbolAddress((void**)&kvph, g_kvph);
    cudaGetSymbolAddress((void**)&biash, g_biash);
    cudaGetSymbolAddress((void**)&aoh, g_aoh);

    const int GEMM_SMEM = 128 * 132 * 4;   // 67584 B
    const int ATTN_SMEM = (2 * 2560 + 2 * 2560 + 256 * 40) * 2;  // 40960 B

    cudaFuncSetAttribute(gemm_h<1>, cudaFuncAttributeMaxDynamicSharedMemorySize, GEMM_SMEM);
    cudaFuncSetAttribute(gemm_h<0>, cudaFuncAttributeMaxDynamicSharedMemorySize, GEMM_SMEM);

    f2h<<<(4194304 + 255) / 256, 256>>>((const float4*)q_w, qwh, 4194304);
    f2h<<<(9437184 + 255) / 256, 256>>>((const float4*)kv_w, kvwh, 9437184);
    f2h<<<(16384 + 255) / 256, 256>>>((const float4*)q_W, wqh, 16384);
    f2h<<<(32768 + 255) / 256, 256>>>((const float4*)kv_W, wkvh, 32768);
    f2h<<<(16384 + 255) / 256, 256>>>((const float4*)proj_W, wph, 16384);
    bias_gather<<<(NQ * NK + 255) / 256, 256>>>(bias_table, rel_index, biash);

    gemm_h<1><<<dim3(2, 512), 256, GEMM_SMEM>>>(qwh, wqh, q_b, qph, 256);
    gemm_h<1><<<dim3(4, 1152), 256, GEMM_SMEM>>>(kvwh, wkvh, kv_b, kvph, 512);
    attn_kernel<<<BATCH * HEADS, 512, ATTN_SMEM>>>(qph, kvph, biash, aoh);
    gemm_h<0><<<dim3(2, 512), 256, GEMM_SMEM>>>(aoh, wph, proj_b, out, 256);
}